// round 2
// baseline (speedup 1.0000x reference)
#include <cuda_runtime.h>
#include <math.h>

// ---- HashGrid config (matches reference) ----
#define NLEVELS 16
#define NFEAT   2
#define TBL     (1u << 19)          // hashmap entries per level
#define NPTS    (64 * 64 * 64)

constexpr double SCALE_ = 1.447269237440378;

// floor(16 * SCALE^l + 1e-6). Repeated-multiply double differs from np pow by
// <1e-11 relative; the +1e-6 guard makes floor identical.
__host__ __device__ constexpr int res_of(int l) {
    double r = 16.0;
    for (int i = 0; i < l; ++i) r *= SCALE_;
    return (int)(r + 1e-6);
}

__global__ __launch_bounds__(256)
void hashgrid_mlp_kernel(const float* __restrict__ pts,
                         const float* __restrict__ table,
                         const float* __restrict__ w1,
                         const float* __restrict__ w2,
                         float* __restrict__ out)
{
    __shared__ float sw1[64 * 32];
    __shared__ float sw2[64];

    const int tid = threadIdx.x;
    for (int k = tid; k < 64 * 32; k += 256) sw1[k] = w1[k];
    if (tid < 64) sw2[tid] = w2[tid];
    __syncthreads();

    const int i = blockIdx.x * 256 + tid;
    if (i >= NPTS) return;

    const float px = pts[3 * i + 0];
    const float py = pts[3 * i + 1];
    const float pz = pts[3 * i + 2];

    float enc[32];

    // compile-time resolutions
    constexpr int RESA[NLEVELS] = {
        res_of(0),  res_of(1),  res_of(2),  res_of(3),
        res_of(4),  res_of(5),  res_of(6),  res_of(7),
        res_of(8),  res_of(9),  res_of(10), res_of(11),
        res_of(12), res_of(13), res_of(14), res_of(15)
    };

#pragma unroll
    for (int l = 0; l < NLEVELS; ++l) {
        const int res = RESA[l];
        // dense iff (res+1)^3 <= T  (res <= 79 for T=2^19)
        const bool dense = ((long long)(res + 1) * (res + 1) * (res + 1) <= (long long)TBL);

        const float fres = (float)res;
        const float x = px * fres, y = py * fres, z = pz * fres;
        const float fx = floorf(x), fy = floorf(y), fz = floorf(z);
        const float tx = x - fx, ty = y - fy, tz = z - fz;
        const unsigned cx = (unsigned)fx, cy = (unsigned)fy, cz = (unsigned)fz;

        const float2* tab = (const float2*)table + (size_t)l * TBL;

        float e0 = 0.f, e1 = 0.f;
#pragma unroll
        for (int c = 0; c < 8; ++c) {
            const unsigned ox = (c >> 2) & 1u;
            const unsigned oy = (c >> 1) & 1u;
            const unsigned oz = c & 1u;
            const unsigned X = cx + ox, Y = cy + oy, Z = cz + oz;
            unsigned idx;
            if (dense) {
                const unsigned r1 = (unsigned)(res + 1);
                idx = X + r1 * (Y + r1 * Z);
            } else {
                idx = X ^ (Y * 2654435761u) ^ (Z * 805459861u);
            }
            idx &= (TBL - 1u);
            const float2 t = __ldg(tab + idx);
            const float w = (ox ? tx : 1.f - tx) *
                            (oy ? ty : 1.f - ty) *
                            (oz ? tz : 1.f - tz);
            e0 = fmaf(w, t.x, e0);
            e1 = fmaf(w, t.y, e1);
        }
        enc[2 * l + 0] = e0;
        enc[2 * l + 1] = e1;
    }

    // ---- tiny MLP: h = relu(enc @ w1^T); out = sigmoid(h @ w2^T) ----
    float acc = 0.f;
#pragma unroll
    for (int j = 0; j < 64; ++j) {
        float h = 0.f;
        const float4* row = (const float4*)(sw1 + j * 32);
#pragma unroll
        for (int k = 0; k < 8; ++k) {
            const float4 v = row[k];
            h = fmaf(enc[4 * k + 0], v.x, h);
            h = fmaf(enc[4 * k + 1], v.y, h);
            h = fmaf(enc[4 * k + 2], v.z, h);
            h = fmaf(enc[4 * k + 3], v.w, h);
        }
        h = fmaxf(h, 0.f);
        acc = fmaf(h, sw2[j], acc);
    }

    out[i] = 1.f / (1.f + expf(-acc));
}

extern "C" void kernel_launch(void* const* d_in, const int* in_sizes, int n_in,
                              void* d_out, int out_size)
{
    const float* pts   = (const float*)d_in[0];   // [N,3]
    const float* table = (const float*)d_in[1];   // [16, 2^19, 2]
    const float* w1    = (const float*)d_in[2];   // [64, 32]
    const float* w2    = (const float*)d_in[3];   // [1, 64]
    float* out = (float*)d_out;                   // [N]

    const int nblk = (NPTS + 255) / 256;
    hashgrid_mlp_kernel<<<nblk, 256>>>(pts, table, w1, w2, out);
}